// round 11
// baseline (speedup 1.0000x reference)
#include <cuda_runtime.h>
#include <stdint.h>

// Problem constants
#define BB_  4
#define SS_  8192
#define EE_  1024
#define HH_  16
#define DD_  64
#define SP_  512
#define MQKV (BB_*SS_)
#define MOUT (BB_*SP_)

// Scratch: tf32 bit patterns everywhere.
// g_q   : [B,H,S',D] row-major (attention A operand, loaded to regs directly)
// g_kf  : K in B-fragment-pair order: (((bh*8+kt)*8 + d/8)*4 + j/16)*128 + frag_idx(j%16, d%8)
// g_vf  : V in B-fragment-pair order: (((bh*8+kt)*8 + j/8)*4 + d/16)*128 + frag_idx(d%16, j%8)
//         (j = key index within 64-key tile kt, d = head dim)
__device__ uint32_t g_q [BB_*HH_*SP_*DD_];
__device__ uint32_t g_kf[BB_*HH_*SP_*DD_];
__device__ uint32_t g_vf[BB_*HH_*SP_*DD_];
__device__ uint32_t g_ctx[BB_*SP_*EE_];       // [B,S',E] tf32 bits
__device__ uint32_t g_wqkv[192*EE_];          // fragment-ordered [Wq;Wk;Wv]
__device__ uint32_t g_wo[EE_*EE_];            // fragment-ordered Wo

// ---------------------------------------------------------------------------
// helpers
// ---------------------------------------------------------------------------
__device__ __forceinline__ uint32_t f2tf32(float f) {
    uint32_t u;
    asm("cvt.rna.tf32.f32 %0, %1;" : "=r"(u) : "f"(f));
    return u;
}

__device__ __forceinline__ void mma_tf32(float c[4], const uint32_t a[4], const uint32_t b[2]) {
    asm volatile(
        "mma.sync.aligned.m16n8k8.row.col.f32.tf32.tf32.f32 "
        "{%0,%1,%2,%3}, {%4,%5,%6,%7}, {%8,%9}, {%0,%1,%2,%3};\n"
        : "+f"(c[0]), "+f"(c[1]), "+f"(c[2]), "+f"(c[3])
        : "r"(a[0]), "r"(a[1]), "r"(a[2]), "r"(a[3]), "r"(b[0]), "r"(b[1]));
}

__device__ __forceinline__ void ldsm_x4(uint32_t r[4], uint32_t addr) {
    asm volatile("ldmatrix.sync.aligned.m8n8.x4.shared.b16 {%0,%1,%2,%3}, [%4];"
                 : "=r"(r[0]), "=r"(r[1]), "=r"(r[2]), "=r"(r[3]) : "r"(addr));
}

__device__ __forceinline__ uint32_t smem_u32(const void* p) {
    return (uint32_t)__cvta_generic_to_shared(p);
}
#define CP16(dst, src) asm volatile("cp.async.cg.shared.global [%0], [%1], 16;\n" :: "r"(dst), "l"(src))
#define CP_COMMIT()    asm volatile("cp.async.commit_group;\n" ::: "memory")
#define CP_WAIT1()     asm volatile("cp.async.wait_group 1;\n" ::: "memory")
#define CP_WAIT0()     asm volatile("cp.async.wait_group 0;\n" ::: "memory")

#define S20 20   // smem row stride (80B): LDSM phases conflict-free, 16B-aligned

// Fragment-pair tile: 16 n-rows x 8 k, 128 u32.
// Within a uint4 at lane*4: {bf0_even, bf1_even, bf0_odd, bf1_odd}.
__device__ __forceinline__ int frag_idx(int n16, int k8) {
    return ((n16 & 7) * 4 + (k8 & 3)) * 4 + ((n16 >> 3) << 1) + (k8 >> 2);
}

// ---------------------------------------------------------------------------
// Kernel 0: pre-convert + pre-swizzle weights (once per launch, ~5us)
// ---------------------------------------------------------------------------
__global__ __launch_bounds__(256)
void cvt_weights(const float* __restrict__ Wq, const float* __restrict__ Wk,
                 const float* __restrict__ Wv, const float* __restrict__ Wo)
{
    const int idx = blockIdx.x * 256 + threadIdx.x;   // 0..65535
    const int row = idx >> 10;
    const int k   = idx & 1023;
    const int it  = k >> 4;
    const int ks  = (k >> 3) & 1;
    const int k8  = k & 7;

    {
        const float* Ws[3] = { Wq, Wk, Wv };
        #pragma unroll
        for (int mat = 0; mat < 3; mat++) {
            int n = mat * 64 + row;
            int addr = ((it * 2 + ks) * 12 + (n >> 4)) * 128 + frag_idx(n & 15, k8);
            g_wqkv[addr] = f2tf32(Ws[mat][row * 1024 + k]);
        }
    }
    #pragma unroll
    for (int j = 0; j < 16; j++) {
        int e  = idx + j * 65536;
        int n  = e >> 10;
        int kk = e & 1023;
        int it2 = kk >> 4, ks2 = (kk >> 3) & 1, k82 = kk & 7;
        int nb = n >> 7, nn = n & 127;
        int addr = (((nb * 64 + it2) * 2 + ks2) * 8 + (nn >> 4)) * 128 + frag_idx(nn & 15, k82);
        g_wo[addr] = f2tf32(Wo[(size_t)n * 1024 + kk]);
    }
}

// ---------------------------------------------------------------------------
// Kernel 1: fused QKV projection (mainloop unchanged from R9).
// Epilogue now writes K/V directly in B-fragment-pair order.
// ---------------------------------------------------------------------------
#define QKV_ASTG (128 * S20)   // 2560 u32
#define QKV_BSTG 3072          // u32
#define QKV_SMEM ((3 * QKV_ASTG + 3 * QKV_BSTG) * 4)

__global__ __launch_bounds__(512)
void qkv_mma(const float* __restrict__ x,
             const float* __restrict__ bq, const float* __restrict__ bk,
             const float* __restrict__ bv)
{
    extern __shared__ uint32_t sm[];
    uint32_t* As = sm;                      // 3 stages of [128][S20]
    uint32_t* Bs = sm + 3 * QKV_ASTG;       // 3 stages of 3072 (fragment order)

    const int tid  = threadIdx.x;
    const int warp = tid >> 5;
    const int lane = tid & 31;
    const int wm   = warp >> 2;
    const int wn   = warp & 3;
    const int m0   = blockIdx.x * 128;
    const int lq   = lane >> 2;
    const int lr   = lane & 3;

    // LDSM per-lane address components
    const int lt       = lane >> 3;
    const int lrw      = lane & 7;
    const int arow_off = (lt & 1) * 8 + lrw;
    const int akoff    = (lt >> 1) * 4;
    uint32_t a_ldsm[3];
    #pragma unroll
    for (int s = 0; s < 3; s++)
        a_ldsm[s] = smem_u32(&As[s * QKV_ASTG + (wm * 32 + arow_off) * S20 + akoff]);

    const int arow = tid >> 2;
    const int ac4  = (tid & 3) * 4;
    const float* a_src = x + (size_t)(m0 + arow) * 1024 + ac4;
    uint32_t a_dst[3];
    #pragma unroll
    for (int s = 0; s < 3; s++)
        a_dst[s] = smem_u32(&As[s * QKV_ASTG + arow * S20 + ac4]);

    const bool has2 = (tid < 256);
    uint32_t b_dst1[3], b_dst2[3];
    #pragma unroll
    for (int s = 0; s < 3; s++) {
        b_dst1[s] = smem_u32(&Bs[s * QKV_BSTG + tid * 4]);
        b_dst2[s] = smem_u32(&Bs[s * QKV_BSTG + (512 + tid) * 4]);
    }

    float acc[2][6][4];
    #pragma unroll
    for (int mt = 0; mt < 2; mt++)
        #pragma unroll
        for (int nt = 0; nt < 6; nt++)
            #pragma unroll
            for (int e = 0; e < 4; e++) acc[mt][nt][e] = 0.f;

    #pragma unroll
    for (int s = 0; s < 2; s++) {
        CP16(a_dst[s], a_src + s * 16);
        CP16(b_dst1[s], g_wqkv + s * QKV_BSTG + tid * 4);
        if (has2) CP16(b_dst2[s], g_wqkv + s * QKV_BSTG + (512 + tid) * 4);
        CP_COMMIT();
    }

    for (int it = 0; it < 64; ++it) {
        CP_WAIT1();
        __syncthreads();

        if (it + 2 < 64) {
            int s = (it + 2) % 3;
            CP16(a_dst[s], a_src + (it + 2) * 16);
            CP16(b_dst1[s], g_wqkv + (it + 2) * QKV_BSTG + tid * 4);
            if (has2) CP16(b_dst2[s], g_wqkv + (it + 2) * QKV_BSTG + (512 + tid) * 4);
        }
        CP_COMMIT();

        const int cur = it % 3;
        const uint32_t* Bc = Bs + cur * QKV_BSTG;
        const uint32_t  Ab = a_ldsm[cur];

        #pragma unroll
        for (int ks = 0; ks < 2; ks++) {
            uint32_t af[2][4];
            #pragma unroll
            for (int mt = 0; mt < 2; mt++) {
                uint32_t raw[4];
                ldsm_x4(raw, Ab + (uint32_t)((mt * 16 * S20 + ks * 8) * 4));
                af[mt][0] = f2tf32(__uint_as_float(raw[0]));
                af[mt][1] = f2tf32(__uint_as_float(raw[1]));
                af[mt][2] = f2tf32(__uint_as_float(raw[2]));
                af[mt][3] = f2tf32(__uint_as_float(raw[3]));
            }
            #pragma unroll
            for (int pl = 0; pl < 3; pl++) {
                uint4 bv = *(const uint4*)&Bc[(ks * 12 + wn * 3 + pl) * 128 + lane * 4];
                uint32_t bfe[2] = { bv.x, bv.y };
                uint32_t bfo[2] = { bv.z, bv.w };
                mma_tf32(acc[0][2*pl  ], af[0], bfe);
                mma_tf32(acc[1][2*pl  ], af[1], bfe);
                mma_tf32(acc[0][2*pl+1], af[0], bfo);
                mma_tf32(acc[1][2*pl+1], af[1], bfo);
            }
        }
    }

    // Epilogue: bias + scatter.  Q row-major; K/V fragment-pair order.
    #pragma unroll
    for (int mt = 0; mt < 2; mt++) {
        #pragma unroll
        for (int half = 0; half < 2; half++) {
            int m  = m0 + wm * 32 + mt * 16 + half * 8 + lq;
            int bb = m >> 13;
            int s  = m & 8191;
            int sp = s >> 4;           // s' (key/query index)
            int h  = s & 15;
            int bh = bb * 16 + h;
            int j  = sp & 63;          // index within 64-key tile
            int bhkt = bh * 8 + (sp >> 6);
            size_t qrowoff = ((size_t)bh * 512 + sp) * 64;
            #pragma unroll
            for (int nt = 0; nt < 6; nt++) {
                int n   = wn * 48 + nt * 8 + 2 * lr;
                int mat = n >> 6;
                int nn  = n & 63;
                const float* bias = (mat == 0) ? bq : (mat == 1 ? bk : bv);
                float v0 = acc[mt][nt][half * 2 + 0] + bias[nn];
                float v1 = acc[mt][nt][half * 2 + 1] + bias[nn + 1];
                if (mat == 0) {
                    uint2 v = { f2tf32(v0), f2tf32(v1) };
                    *(uint2*)(g_q + qrowoff + nn) = v;
                } else if (mat == 1) {
                    // K: n-dim = key j, k-dim = d = nn  (nn, nn+1 share d/8)
                    int base = ((bhkt * 8 + (nn >> 3)) * 4 + (j >> 4)) * 128;
                    g_kf[base + frag_idx(j & 15, nn & 7)]       = f2tf32(v0);
                    g_kf[base + frag_idx(j & 15, (nn + 1) & 7)] = f2tf32(v1);
                } else {
                    // V: n-dim = d = nn, k-dim = key j  (nn, nn+1 share d/16)
                    int base = ((bhkt * 8 + (j >> 3)) * 4 + (nn >> 4)) * 128;
                    g_vf[base + frag_idx(nn & 15, j & 7)]       = f2tf32(v0);
                    g_vf[base + frag_idx((nn + 1) & 15, j & 7)] = f2tf32(v1);
                }
            }
        }
    }
}

// ---------------------------------------------------------------------------
// Kernel 2: attention.  K/V arrive fragment-ordered: linear cp.async staging
// (double-buffered) + LDS.128 fragment loads.  Q frags from g_q (row-major).
// ---------------------------------------------------------------------------
#define AT_STG 4096                     // u32 per K (or V) kt-tile
#define AT_SMEM (4 * AT_STG * 4)        // 2 bufs x (K+V) = 64 KB

__global__ __launch_bounds__(256)
void attn_mma()
{
    extern __shared__ uint32_t smA[];
    uint32_t* Kf = smA;                 // [2][AT_STG]
    uint32_t* Vf = smA + 2 * AT_STG;    // [2][AT_STG]

    const int bh   = blockIdx.x;
    const int qt   = blockIdx.y;
    const int tid  = threadIdx.x;
    const int warp = tid >> 5;
    const int lane = tid & 31;
    const int lq   = lane >> 2;
    const int lr   = lane & 3;

    // Q fragments (A operand), scaled by 1/8 (exact on tf32 values)
    const uint32_t* qbase = g_q + ((size_t)bh * 512 + qt * 128 + warp * 16) * 64;
    uint32_t qa[8][4];
    #pragma unroll
    for (int ks = 0; ks < 8; ks++) {
        qa[ks][0] = __float_as_uint(__uint_as_float(qbase[(size_t)lq       * 64 + ks * 8 + lr    ]) * 0.125f);
        qa[ks][1] = __float_as_uint(__uint_as_float(qbase[(size_t)(lq + 8) * 64 + ks * 8 + lr    ]) * 0.125f);
        qa[ks][2] = __float_as_uint(__uint_as_float(qbase[(size_t)lq       * 64 + ks * 8 + lr + 4]) * 0.125f);
        qa[ks][3] = __float_as_uint(__uint_as_float(qbase[(size_t)(lq + 8) * 64 + ks * 8 + lr + 4]) * 0.125f);
    }

    float o[8][4];
    #pragma unroll
    for (int nt = 0; nt < 8; nt++)
        #pragma unroll
        for (int e = 0; e < 4; e++) o[nt][e] = 0.f;
    float lsum0 = 0.f, lsum1 = 0.f;

    const uint32_t* kb = g_kf + (size_t)bh * 32768;   // 8 kt-tiles x 4096
    const uint32_t* vb = g_vf + (size_t)bh * 32768;

    // staging: 1024 16B-chunks per tile / 256 thr = 4 each (per K and V)
    uint32_t kdst[2], vdst[2];
    kdst[0] = smem_u32(&Kf[0]);          kdst[1] = smem_u32(&Kf[AT_STG]);
    vdst[0] = smem_u32(&Vf[0]);          vdst[1] = smem_u32(&Vf[AT_STG]);

    // prologue: tile 0 -> buf 0
    #pragma unroll
    for (int i = 0; i < 4; i++) {
        int c = (tid + i * 256) * 4;
        CP16(kdst[0] + c * 4, kb + c);
        CP16(vdst[0] + c * 4, vb + c);
    }
    CP_COMMIT();

    for (int kt = 0; kt < 8; kt++) {
        CP_WAIT0();
        __syncthreads();

        if (kt < 7) {
            const uint32_t* kn = kb + (kt + 1) * AT_STG;
            const uint32_t* vn = vb + (kt + 1) * AT_STG;
            int nbuf = (kt + 1) & 1;
            #pragma unroll
            for (int i = 0; i < 4; i++) {
                int c = (tid + i * 256) * 4;
                CP16(kdst[nbuf] + c * 4, kn + c);
                CP16(vdst[nbuf] + c * 4, vn + c);
            }
            CP_COMMIT();
        }

        const uint32_t* Kc = Kf + (kt & 1) * AT_STG;
        const uint32_t* Vc = Vf + (kt & 1) * AT_STG;

        // S = Q @ K^T : 32 LDS.128 + 64 MMA
        float sc[8][4];
        #pragma unroll
        for (int nt = 0; nt < 8; nt++)
            sc[nt][0] = sc[nt][1] = sc[nt][2] = sc[nt][3] = 0.f;
        #pragma unroll
        for (int ks = 0; ks < 8; ks++) {
            #pragma unroll
            for (int p = 0; p < 4; p++) {
                uint4 bv = *(const uint4*)&Kc[(ks * 4 + p) * 128 + lane * 4];
                uint32_t bfe[2] = { bv.x, bv.y };
                uint32_t bfo[2] = { bv.z, bv.w };
                mma_tf32(sc[2*p    ], qa[ks], bfe);
                mma_tf32(sc[2*p + 1], qa[ks], bfo);
            }
        }

        // exp + partial row sums
        #pragma unroll
        for (int nt = 0; nt < 8; nt++) {
            float p0 = __expf(sc[nt][0]), p1 = __expf(sc[nt][1]);
            float p2 = __expf(sc[nt][2]), p3 = __expf(sc[nt][3]);
            sc[nt][0] = p0; sc[nt][1] = p1; sc[nt][2] = p2; sc[nt][3] = p3;
            lsum0 += p0 + p1;
            lsum1 += p2 + p3;
        }

        // P @ V : shfl remap + 32 LDS.128 + 64 MMA
        #pragma unroll
        for (int ks = 0; ks < 8; ks++) {
            int src  = (lane & ~3) | (lr >> 1);
            float t0 = __shfl_sync(0xffffffffu, sc[ks][0], src);
            float t1 = __shfl_sync(0xffffffffu, sc[ks][1], src);
            float t2 = __shfl_sync(0xffffffffu, sc[ks][2], src);
            float t3 = __shfl_sync(0xffffffffu, sc[ks][3], src);
            float u0 = __shfl_sync(0xffffffffu, sc[ks][0], src + 2);
            float u1 = __shfl_sync(0xffffffffu, sc[ks][1], src + 2);
            float u2 = __shfl_sync(0xffffffffu, sc[ks][2], src + 2);
            float u3 = __shfl_sync(0xffffffffu, sc[ks][3], src + 2);
            uint32_t pa[4];
            pa[0] = f2tf32((lr & 1) ? t1 : t0);
            pa[1] = f2tf32((lr & 1) ? t3 : t2);
            pa[2] = f2tf32((lr & 1) ? u1 : u0);
            pa[3] = f2tf32((lr & 1) ? u3 : u2);
            #pragma unroll
            for (int p = 0; p < 4; p++) {
                uint4 bv = *(const uint4*)&Vc[(ks * 4 + p) * 128 + lane * 4];
                uint32_t bfe[2] = { bv.x, bv.y };
                uint32_t bfo[2] = { bv.z, bv.w };
                mma_tf32(o[2*p    ], pa, bfe);
                mma_tf32(o[2*p + 1], pa, bfo);
            }
        }
        __syncthreads();   // readers done before next staging overwrites
    }

    lsum0 += __shfl_xor_sync(0xffffffffu, lsum0, 1);
    lsum0 += __shfl_xor_sync(0xffffffffu, lsum0, 2);
    lsum1 += __shfl_xor_sync(0xffffffffu, lsum1, 1);
    lsum1 += __shfl_xor_sync(0xffffffffu, lsum1, 2);
    const float inv0 = 1.f / lsum0;
    const float inv1 = 1.f / lsum1;

    const int bb = bh >> 4, h = bh & 15;
    const int qrow0 = qt * 128 + warp * 16 + lq;
    uint32_t* out0 = g_ctx + ((size_t)(bb * 512 + qrow0)) * 1024 + h * 64;
    uint32_t* out1 = out0 + (size_t)8 * 1024;
    #pragma unroll
    for (int ntd = 0; ntd < 8; ntd++) {
        uint2 v0 = { f2tf32(o[ntd][0] * inv0), f2tf32(o[ntd][1] * inv0) };
        uint2 v1 = { f2tf32(o[ntd][2] * inv1), f2tf32(o[ntd][3] * inv1) };
        *(uint2*)(out0 + ntd * 8 + 2 * lr) = v0;
        *(uint2*)(out1 + ntd * 8 + 2 * lr) = v1;
    }
}

// ---------------------------------------------------------------------------
// Kernel 3: output projection (unchanged from R9).
// ---------------------------------------------------------------------------
#define OP_ASTG (128 * S20)   // 2560 u32
#define OP_BSTG 2048          // u32
#define OP_SMEM ((3 * OP_ASTG + 3 * OP_BSTG) * 4)

__global__ __launch_bounds__(512)
void outproj_mma(const float* __restrict__ bo, float* __restrict__ out)
{
    extern __shared__ uint32_t sm[];
    uint32_t* As = sm;
    uint32_t* Bs = sm + 3 * OP_ASTG;

    const int tid  = threadIdx.x;
    const int warp = tid >> 5;
    const int lane = tid & 31;
    const int wm   = warp >> 2;
    const int wn   = warp & 3;
    const int m0   = blockIdx.x * 128;
    const int nb   = blockIdx.y;
    const int lq   = lane >> 2;
    const int lr   = lane & 3;

    const int lt       = lane >> 3;
    const int lrw      = lane & 7;
    const int arow_off = (lt & 1) * 8 + lrw;
    const int akoff    = (lt >> 1) * 4;
    uint32_t a_ldsm[3];
    #pragma unroll
    for (int s = 0; s < 3; s++)
        a_ldsm[s] = smem_u32(&As[s * OP_ASTG + (wm * 32 + arow_off) * S20 + akoff]);

    const int arow = tid >> 2;
    const int ac4  = (tid & 3) * 4;
    const uint32_t* a_src = g_ctx + (size_t)(m0 + arow) * 1024 + ac4;
    uint32_t a_dst[3], b_dst[3];
    #pragma unroll
    for (int s = 0; s < 3; s++) {
        a_dst[s] = smem_u32(&As[s * OP_ASTG + arow * S20 + ac4]);
        b_dst[s] = smem_u32(&Bs[s * OP_BSTG + tid * 4]);
    }
    const uint32_t* b_base = g_wo + (size_t)nb * 64 * OP_BSTG;

    float acc[2][4][4];
    #pragma unroll
    for (int mt = 0; mt < 2; mt++)
        #pragma unroll
        for (int nt = 0; nt < 4; nt++)
            #pragma unroll
            for (int e = 0; e < 4; e++) acc[mt][nt][e] = 0.f;

    #pragma unroll
    for (int s = 0; s < 2; s++) {
        CP16(a_dst[s], a_src + s * 16);
        CP16(b_dst[s], b_base + s * OP_BSTG + tid * 4);
        CP_COMMIT();
    }

    for (int it = 0; it < 64; ++it) {
        CP_WAIT1();
        __syncthreads();

        if (it + 2 < 64) {
            int s = (it + 2) % 3;
            CP16(a_dst[s], a_src + (it + 2) * 16);
            CP16(b_dst[s], b_base + (size_t)(it + 2) * OP_BSTG + tid * 4);
        }
        CP_COMMIT();

        const int cur = it % 3;
        const uint32_t* Bc = Bs + cur * OP_BSTG;
        const uint32_t  Ab = a_ldsm[cur];

        #pragma unroll
        for (int ks = 0; ks < 2; ks++) {
            uint32_t af[2][4];
            #pragma unroll
            for (int mt = 0; mt < 2; mt++)
                ldsm_x4(af[mt], Ab + (uint32_t)((mt * 16 * S20 + ks * 8) * 4));
            #pragma unroll
            for (int pl = 0; pl < 2; pl++) {
                uint4 bv = *(const uint4*)&Bc[(ks * 8 + wn * 2 + pl) * 128 + lane * 4];
                uint32_t bfe[2] = { bv.x, bv.y };
                uint32_t bfo[2] = { bv.z, bv.w };
                mma_tf32(acc[0][2*pl  ], af[0], bfe);
                mma_tf32(acc[1][2*pl  ], af[1], bfe);
                mma_tf32(acc[0][2*pl+1], af[0], bfo);
                mma_tf32(acc[1][2*pl+1], af[1], bfo);
            }
        }
    }

    #pragma unroll
    for (int mt = 0; mt < 2; mt++) {
        #pragma unroll
        for (int half = 0; half < 2; half++) {
            int m = m0 + wm * 32 + mt * 16 + half * 8 + lq;
            float* rowp = out + (size_t)m * 1024 + nb * 128;
            #pragma unroll
            for (int nt = 0; nt < 4; nt++) {
                int n = wn * 32 + nt * 8 + 2 * lr;
                float2 v;
                v.x = acc[mt][nt][half * 2 + 0] + bo[nb * 128 + n];
                v.y = acc[mt][nt][half * 2 + 1] + bo[nb * 128 + n + 1];
                *(float2*)(rowp + n) = v;
            }
        }
    }
}

// ---------------------------------------------------------------------------
extern "C" void kernel_launch(void* const* d_in, const int* in_sizes, int n_in,
                              void* d_out, int out_size)
{
    const float* x  = (const float*)d_in[0];
    const float* Wq = (const float*)d_in[1];
    const float* bq = (const float*)d_in[2];
    const float* Wk = (const float*)d_in[3];
    const float* bk = (const float*)d_in[4];
    const float* Wv = (const float*)d_in[5];
    const float* bv = (const float*)d_in[6];
    const float* Wo = (const float*)d_in[7];
    const float* bo = (const float*)d_in[8];
    float* out = (float*)d_out;

    static bool attr_done = false;
    if (!attr_done) {
        cudaFuncSetAttribute(qkv_mma, cudaFuncAttributeMaxDynamicSharedMemorySize, QKV_SMEM);
        cudaFuncSetAttribute(attn_mma, cudaFuncAttributeMaxDynamicSharedMemorySize, AT_SMEM);
        cudaFuncSetAttribute(outproj_mma, cudaFuncAttributeMaxDynamicSharedMemorySize, OP_SMEM);
        attr_done = true;
    }

    cvt_weights<<<256, 256>>>(Wq, Wk, Wv, Wo);

    qkv_mma<<<MQKV / 128, 512, QKV_SMEM>>>(x, bq, bk, bv);

    dim3 g2(BB_ * HH_, SP_ / 128);
    attn_mma<<<g2, 256, AT_SMEM>>>();

    dim3 g3(MOUT / 128, EE_ / 128);
    outproj_mma<<<g3, 512, OP_SMEM>>>(bo, out);
}

// round 12
// speedup vs baseline: 1.1149x; 1.1149x over previous
#include <cuda_runtime.h>
#include <stdint.h>

// Problem constants
#define BB_  4
#define SS_  8192
#define EE_  1024
#define HH_  16
#define DD_  64
#define SP_  512
#define MQKV (BB_*SS_)
#define MOUT (BB_*SP_)

// Scratch: q/k/v/ctx hold tf32 bit patterns; weights pre-converted AND
// pre-swizzled into mma-fragment order.
__device__ uint32_t g_q[BB_*HH_*SP_*DD_];     // [B,H,S',D] tf32 bits
__device__ uint32_t g_k[BB_*HH_*SP_*DD_];
__device__ uint32_t g_v[BB_*HH_*SP_*DD_];
__device__ uint32_t g_ctx[BB_*SP_*EE_];       // [B,S',E]  tf32 bits
__device__ uint32_t g_wqkv[192*EE_];          // fragment-ordered [Wq;Wk;Wv]
__device__ uint32_t g_wo[EE_*EE_];            // fragment-ordered Wo (64-wide n-blocks)

// ---------------------------------------------------------------------------
// helpers
// ---------------------------------------------------------------------------
__device__ __forceinline__ uint32_t f2tf32(float f) {
    uint32_t u;
    asm("cvt.rna.tf32.f32 %0, %1;" : "=r"(u) : "f"(f));
    return u;
}

__device__ __forceinline__ void mma_tf32(float c[4], const uint32_t a[4], const uint32_t b[2]) {
    asm volatile(
        "mma.sync.aligned.m16n8k8.row.col.f32.tf32.tf32.f32 "
        "{%0,%1,%2,%3}, {%4,%5,%6,%7}, {%8,%9}, {%0,%1,%2,%3};\n"
        : "+f"(c[0]), "+f"(c[1]), "+f"(c[2]), "+f"(c[3])
        : "r"(a[0]), "r"(a[1]), "r"(a[2]), "r"(a[3]), "r"(b[0]), "r"(b[1]));
}

__device__ __forceinline__ void ldsm_x4(uint32_t r[4], uint32_t addr) {
    asm volatile("ldmatrix.sync.aligned.m8n8.x4.shared.b16 {%0,%1,%2,%3}, [%4];"
                 : "=r"(r[0]), "=r"(r[1]), "=r"(r[2]), "=r"(r[3]) : "r"(addr));
}

__device__ __forceinline__ uint32_t smem_u32(const void* p) {
    return (uint32_t)__cvta_generic_to_shared(p);
}
#define CP16(dst, src) asm volatile("cp.async.cg.shared.global [%0], [%1], 16;\n" :: "r"(dst), "l"(src))
#define CP_COMMIT()    asm volatile("cp.async.commit_group;\n" ::: "memory")
#define CP_WAIT1()     asm volatile("cp.async.wait_group 1;\n" ::: "memory")

#define S20 20   // smem row stride (80B): LDSM phases conflict-free, 16B-aligned

// Fragment-pair tile: 16 n-rows x 8 k, 128 u32.
__device__ __forceinline__ int frag_idx(int n16, int k8) {
    return ((n16 & 7) * 4 + (k8 & 3)) * 4 + ((n16 >> 3) << 1) + (k8 >> 2);
}

// ---------------------------------------------------------------------------
// Kernel 0: pre-convert + pre-swizzle weights (once per launch, ~5us)
// g_wqkv: addr = ((it*2+ks)*12 + n/16)*128 + frag_idx(n%16, k%8)
// g_wo  : nb=n/64, nn=n%64: addr = (((nb*64+it)*2+ks)*4 + nn/16)*128 + frag_idx(nn%16,k%8)
// ---------------------------------------------------------------------------
__global__ __launch_bounds__(256)
void cvt_weights(const float* __restrict__ Wq, const float* __restrict__ Wk,
                 const float* __restrict__ Wv, const float* __restrict__ Wo)
{
    const int idx = blockIdx.x * 256 + threadIdx.x;   // 0..65535
    const int row = idx >> 10;
    const int k   = idx & 1023;
    const int it  = k >> 4;
    const int ks  = (k >> 3) & 1;
    const int k8  = k & 7;

    {
        const float* Ws[3] = { Wq, Wk, Wv };
        #pragma unroll
        for (int mat = 0; mat < 3; mat++) {
            int n = mat * 64 + row;
            int addr = ((it * 2 + ks) * 12 + (n >> 4)) * 128 + frag_idx(n & 15, k8);
            g_wqkv[addr] = f2tf32(Ws[mat][row * 1024 + k]);
        }
    }
    #pragma unroll
    for (int j = 0; j < 16; j++) {
        int e  = idx + j * 65536;
        int n  = e >> 10;
        int kk = e & 1023;
        int it2 = kk >> 4, ks2 = (kk >> 3) & 1, k82 = kk & 7;
        int nb = n >> 6, nn = n & 63;
        int addr = (((nb * 64 + it2) * 2 + ks2) * 4 + (nn >> 4)) * 128 + frag_idx(nn & 15, k82);
        g_wo[addr] = f2tf32(Wo[(size_t)n * 1024 + kk]);
    }
}

// ---------------------------------------------------------------------------
// Kernel 1: fused QKV projection.  BM=64, BN=192, BK=16, 256 thr / 8 warps,
// warp tile 32m x 48n (wm=warp>>2 in 0..1, wn=warp&3).  Grid 512 -> 2 CTAs/SM.
// A: row-major fp32 smem -> LDSM.x4 -> CVT.  B: fragment-ordered -> LDS.128.
// ---------------------------------------------------------------------------
#define QKV_ASTG (64 * S20)    // 1280 u32
#define QKV_BSTG 3072          // u32
#define QKV_SMEM ((3 * QKV_ASTG + 3 * QKV_BSTG) * 4)   // 52.2 KB

__global__ __launch_bounds__(256)
void qkv_mma(const float* __restrict__ x,
             const float* __restrict__ bq, const float* __restrict__ bk,
             const float* __restrict__ bv)
{
    extern __shared__ uint32_t sm[];
    uint32_t* As = sm;                      // 3 stages of [64][S20]
    uint32_t* Bs = sm + 3 * QKV_ASTG;       // 3 stages of 3072 (fragment order)

    const int tid  = threadIdx.x;
    const int warp = tid >> 5;
    const int lane = tid & 31;
    const int wm   = warp >> 2;           // 0..1
    const int wn   = warp & 3;            // 0..3
    const int m0   = blockIdx.x * 64;
    const int lq   = lane >> 2;
    const int lr   = lane & 3;

    // LDSM per-lane address components
    const int lt       = lane >> 3;
    const int lrw      = lane & 7;
    const int arow_off = (lt & 1) * 8 + lrw;
    const int akoff    = (lt >> 1) * 4;
    uint32_t a_ldsm[3];
    #pragma unroll
    for (int s = 0; s < 3; s++)
        a_ldsm[s] = smem_u32(&As[s * QKV_ASTG + (wm * 32 + arow_off) * S20 + akoff]);

    // A tile: 64x16 = 256 float4, 1 per thread
    const int arow = tid >> 2;
    const int ac4  = (tid & 3) * 4;
    const float* a_src = x + (size_t)(m0 + arow) * 1024 + ac4;
    uint32_t a_dst[3];
    #pragma unroll
    for (int s = 0; s < 3; s++)
        a_dst[s] = smem_u32(&As[s * QKV_ASTG + arow * S20 + ac4]);

    // B tile: 768 16B-chunks, 3 per thread (chunks tid, 256+tid, 512+tid)
    uint32_t b_dst[3][3];
    #pragma unroll
    for (int s = 0; s < 3; s++)
        #pragma unroll
        for (int t = 0; t < 3; t++)
            b_dst[t][s] = smem_u32(&Bs[s * QKV_BSTG + (t * 256 + tid) * 4]);

    float acc[2][6][4];
    #pragma unroll
    for (int mt = 0; mt < 2; mt++)
        #pragma unroll
        for (int nt = 0; nt < 6; nt++)
            #pragma unroll
            for (int e = 0; e < 4; e++) acc[mt][nt][e] = 0.f;

    #pragma unroll
    for (int s = 0; s < 2; s++) {
        CP16(a_dst[s], a_src + s * 16);
        #pragma unroll
        for (int t = 0; t < 3; t++)
            CP16(b_dst[t][s], g_wqkv + s * QKV_BSTG + (t * 256 + tid) * 4);
        CP_COMMIT();
    }

    for (int it = 0; it < 64; ++it) {
        CP_WAIT1();
        __syncthreads();

        if (it + 2 < 64) {
            int s = (it + 2) % 3;
            CP16(a_dst[s], a_src + (it + 2) * 16);
            #pragma unroll
            for (int t = 0; t < 3; t++)
                CP16(b_dst[t][s], g_wqkv + (it + 2) * QKV_BSTG + (t * 256 + tid) * 4);
        }
        CP_COMMIT();

        const int cur = it % 3;
        const uint32_t* Bc = Bs + cur * QKV_BSTG;
        const uint32_t  Ab = a_ldsm[cur];

        #pragma unroll
        for (int ks = 0; ks < 2; ks++) {
            uint32_t af[2][4];
            #pragma unroll
            for (int mt = 0; mt < 2; mt++) {
                uint32_t raw[4];
                ldsm_x4(raw, Ab + (uint32_t)((mt * 16 * S20 + ks * 8) * 4));
                af[mt][0] = f2tf32(__uint_as_float(raw[0]));
                af[mt][1] = f2tf32(__uint_as_float(raw[1]));
                af[mt][2] = f2tf32(__uint_as_float(raw[2]));
                af[mt][3] = f2tf32(__uint_as_float(raw[3]));
            }
            #pragma unroll
            for (int pl = 0; pl < 3; pl++) {
                uint4 bv = *(const uint4*)&Bc[(ks * 12 + wn * 3 + pl) * 128 + lane * 4];
                uint32_t bfe[2] = { bv.x, bv.y };
                uint32_t bfo[2] = { bv.z, bv.w };
                mma_tf32(acc[0][2*pl  ], af[0], bfe);
                mma_tf32(acc[1][2*pl  ], af[1], bfe);
                mma_tf32(acc[0][2*pl+1], af[0], bfo);
                mma_tf32(acc[1][2*pl+1], af[1], bfo);
            }
        }
    }

    // Epilogue: bias + scatter into [B,H,S',D] as tf32 bits (row-major)
    #pragma unroll
    for (int mt = 0; mt < 2; mt++) {
        #pragma unroll
        for (int half = 0; half < 2; half++) {
            int m  = m0 + wm * 32 + mt * 16 + half * 8 + lq;
            int bb = m >> 13;
            int s  = m & 8191;
            int sp = s >> 4;
            int h  = s & 15;
            size_t rowoff = ((size_t)(bb * 16 + h) * 512 + sp) * 64;
            #pragma unroll
            for (int nt = 0; nt < 6; nt++) {
                int n   = wn * 48 + nt * 8 + 2 * lr;
                int mat = n >> 6;
                int nn  = n & 63;
                uint32_t* dst = (mat == 0) ? g_q : (mat == 1 ? g_k : g_v);
                const float* bias = (mat == 0) ? bq : (mat == 1 ? bk : bv);
                uint2 v;
                v.x = f2tf32(acc[mt][nt][half * 2 + 0] + bias[nn]);
                v.y = f2tf32(acc[mt][nt][half * 2 + 1] + bias[nn + 1]);
                *(uint2*)(dst + rowoff + nn) = v;
            }
        }
    }
}

// ---------------------------------------------------------------------------
// Kernel 2: attention (R9 version — tf32 bits in, tf32 bits out).
// ---------------------------------------------------------------------------
#define KSTR 68
#define VSTR 72

__global__ __launch_bounds__(256)
void attn_mma()
{
    __shared__ uint32_t Ks[64 * KSTR];
    __shared__ uint32_t Vs[64 * VSTR];

    const int bh   = blockIdx.x;
    const int qt   = blockIdx.y;
    const int tid  = threadIdx.x;
    const int warp = tid >> 5;
    const int lane = tid & 31;
    const int lq   = lane >> 2;
    const int lr   = lane & 3;

    const uint32_t* qbase = g_q + ((size_t)bh * 512 + qt * 128 + warp * 16) * 64;
    uint32_t qa[8][4];
    #pragma unroll
    for (int ks = 0; ks < 8; ks++) {
        qa[ks][0] = __float_as_uint(__uint_as_float(qbase[(size_t)lq       * 64 + ks * 8 + lr    ]) * 0.125f);
        qa[ks][1] = __float_as_uint(__uint_as_float(qbase[(size_t)(lq + 8) * 64 + ks * 8 + lr    ]) * 0.125f);
        qa[ks][2] = __float_as_uint(__uint_as_float(qbase[(size_t)lq       * 64 + ks * 8 + lr + 4]) * 0.125f);
        qa[ks][3] = __float_as_uint(__uint_as_float(qbase[(size_t)(lq + 8) * 64 + ks * 8 + lr + 4]) * 0.125f);
    }

    float o[8][4];
    #pragma unroll
    for (int nt = 0; nt < 8; nt++)
        #pragma unroll
        for (int e = 0; e < 4; e++) o[nt][e] = 0.f;
    float lsum0 = 0.f, lsum1 = 0.f;

    const uint32_t* kb = g_k + (size_t)bh * 512 * 64;
    const uint32_t* vb = g_v + (size_t)bh * 512 * 64;

    for (int kt = 0; kt < 8; kt++) {
        __syncthreads();
        #pragma unroll
        for (int i = 0; i < 4; i++) {
            int idx = tid + i * 256;
            int row = idx >> 4, c4 = (idx & 15) << 2;
            *(uint4*)(Ks + row * KSTR + c4) = *(const uint4*)(kb + (size_t)kt * 4096 + idx * 4);
            *(uint4*)(Vs + row * VSTR + c4) = *(const uint4*)(vb + (size_t)kt * 4096 + idx * 4);
        }
        __syncthreads();

        float sc[8][4];
        #pragma unroll
        for (int nt = 0; nt < 8; nt++) {
            sc[nt][0] = sc[nt][1] = sc[nt][2] = sc[nt][3] = 0.f;
            #pragma unroll
            for (int ks = 0; ks < 8; ks++) {
                uint32_t bf[2];
                bf[0] = Ks[(nt * 8 + lq) * KSTR + ks * 8 + lr    ];
                bf[1] = Ks[(nt * 8 + lq) * KSTR + ks * 8 + lr + 4];
                mma_tf32(sc[nt], qa[ks], bf);
            }
        }

        #pragma unroll
        for (int nt = 0; nt < 8; nt++) {
            float p0 = __expf(sc[nt][0]), p1 = __expf(sc[nt][1]);
            float p2 = __expf(sc[nt][2]), p3 = __expf(sc[nt][3]);
            sc[nt][0] = p0; sc[nt][1] = p1; sc[nt][2] = p2; sc[nt][3] = p3;
            lsum0 += p0 + p1;
            lsum1 += p2 + p3;
        }

        #pragma unroll
        for (int ks = 0; ks < 8; ks++) {
            int src  = (lane & ~3) | (lr >> 1);
            float t0 = __shfl_sync(0xffffffffu, sc[ks][0], src);
            float t1 = __shfl_sync(0xffffffffu, sc[ks][1], src);
            float t2 = __shfl_sync(0xffffffffu, sc[ks][2], src);
            float t3 = __shfl_sync(0xffffffffu, sc[ks][3], src);
            float u0 = __shfl_sync(0xffffffffu, sc[ks][0], src + 2);
            float u1 = __shfl_sync(0xffffffffu, sc[ks][1], src + 2);
            float u2 = __shfl_sync(0xffffffffu, sc[ks][2], src + 2);
            float u3 = __shfl_sync(0xffffffffu, sc[ks][3], src + 2);
            uint32_t pa[4];
            pa[0] = f2tf32((lr & 1) ? t1 : t0);
            pa[1] = f2tf32((lr & 1) ? t3 : t2);
            pa[2] = f2tf32((lr & 1) ? u1 : u0);
            pa[3] = f2tf32((lr & 1) ? u3 : u2);
            #pragma unroll
            for (int ntd = 0; ntd < 8; ntd++) {
                uint32_t bf[2];
                bf[0] = Vs[(ks * 8 + lr    ) * VSTR + ntd * 8 + lq];
                bf[1] = Vs[(ks * 8 + lr + 4) * VSTR + ntd * 8 + lq];
                mma_tf32(o[ntd], pa, bf);
            }
        }
    }

    lsum0 += __shfl_xor_sync(0xffffffffu, lsum0, 1);
    lsum0 += __shfl_xor_sync(0xffffffffu, lsum0, 2);
    lsum1 += __shfl_xor_sync(0xffffffffu, lsum1, 1);
    lsum1 += __shfl_xor_sync(0xffffffffu, lsum1, 2);
    const float inv0 = 1.f / lsum0;
    const float inv1 = 1.f / lsum1;

    const int bb = bh >> 4, h = bh & 15;
    const int qrow0 = qt * 128 + warp * 16 + lq;
    uint32_t* out0 = g_ctx + ((size_t)(bb * 512 + qrow0)) * 1024 + h * 64;
    uint32_t* out1 = out0 + (size_t)8 * 1024;
    #pragma unroll
    for (int ntd = 0; ntd < 8; ntd++) {
        uint2 v0 = { f2tf32(o[ntd][0] * inv0), f2tf32(o[ntd][1] * inv0) };
        uint2 v1 = { f2tf32(o[ntd][2] * inv1), f2tf32(o[ntd][3] * inv1) };
        *(uint2*)(out0 + ntd * 8 + 2 * lr) = v0;
        *(uint2*)(out1 + ntd * 8 + 2 * lr) = v1;
    }
}

// ---------------------------------------------------------------------------
// Kernel 3: output projection.  BM=128, BN=64, BK=16, 256 thr / 8 warps,
// warp tile 32m x 32n (wm=warp>>1, wn=warp&1).  Grid 256 -> 2 CTAs/SM.
// A (ctx, tf32) -> LDSM.x4, no CVT.  B (Wo) fragment-ordered -> LDS.128.
// ---------------------------------------------------------------------------
#define OP_ASTG (128 * S20)   // 2560 u32
#define OP_BSTG 1024          // u32 (4 pair-tiles x 2 ks x 128)
#define OP_SMEM ((3 * OP_ASTG + 3 * OP_BSTG) * 4)   // 43 KB

__global__ __launch_bounds__(256)
void outproj_mma(const float* __restrict__ bo, float* __restrict__ out)
{
    extern __shared__ uint32_t sm[];
    uint32_t* As = sm;
    uint32_t* Bs = sm + 3 * OP_ASTG;

    const int tid  = threadIdx.x;
    const int warp = tid >> 5;
    const int lane = tid & 31;
    const int wm   = warp >> 1;           // 0..3
    const int wn   = warp & 1;            // 0..1
    const int m0   = blockIdx.x * 128;
    const int nb   = blockIdx.y;          // 64-wide n block, 0..15
    const int lq   = lane >> 2;
    const int lr   = lane & 3;

    const int lt       = lane >> 3;
    const int lrw      = lane & 7;
    const int arow_off = (lt & 1) * 8 + lrw;
    const int akoff    = (lt >> 1) * 4;
    uint32_t a_ldsm[3];
    #pragma unroll
    for (int s = 0; s < 3; s++)
        a_ldsm[s] = smem_u32(&As[s * OP_ASTG + (wm * 32 + arow_off) * S20 + akoff]);

    // A: 128x16 = 512 f4, 2 per thread (chunks tid, 256+tid)
    uint32_t a_dst[2][3], b_dst[3];
    const uint32_t* a_srcs[2];
    #pragma unroll
    for (int t = 0; t < 2; t++) {
        int c   = t * 256 + tid;
        int row = c >> 2, c4 = (c & 3) * 4;
        a_srcs[t] = g_ctx + (size_t)(m0 + row) * 1024 + c4;
        #pragma unroll
        for (int s = 0; s < 3; s++)
            a_dst[t][s] = smem_u32(&As[s * OP_ASTG + row * S20 + c4]);
    }
    // B: 256 f4, 1 per thread
    #pragma unroll
    for (int s = 0; s < 3; s++)
        b_dst[s] = smem_u32(&Bs[s * OP_BSTG + tid * 4]);
    const uint32_t* b_base = g_wo + (size_t)nb * 64 * OP_BSTG;

    float acc[2][4][4];
    #pragma unroll
    for (int mt = 0; mt < 2; mt++)
        #pragma unroll
        for (int nt = 0; nt < 4; nt++)
            #pragma unroll
            for (int e = 0; e < 4; e++) acc[mt][nt][e] = 0.f;

    #pragma unroll
    for (int s = 0; s < 2; s++) {
        #pragma unroll
        for (int t = 0; t < 2; t++) CP16(a_dst[t][s], a_srcs[t] + s * 16);
        CP16(b_dst[s], b_base + s * OP_BSTG + tid * 4);
        CP_COMMIT();
    }

    for (int it = 0; it < 64; ++it) {
        CP_WAIT1();
        __syncthreads();

        if (it + 2 < 64) {
            int s = (it + 2) % 3;
            #pragma unroll
            for (int t = 0; t < 2; t++) CP16(a_dst[t][s], a_srcs[t] + (it + 2) * 16);
            CP16(b_dst[s], b_base + (size_t)(it + 2) * OP_BSTG + tid * 4);
        }
        CP_COMMIT();

        const int cur = it % 3;
        const uint32_t* Bc = Bs + cur * OP_BSTG;
        const uint32_t  Ab = a_ldsm[cur];

        #pragma unroll
        for (int ks = 0; ks < 2; ks++) {
            uint32_t af[2][4];
            #pragma unroll
            for (int mt = 0; mt < 2; mt++)
                ldsm_x4(af[mt], Ab + (uint32_t)((mt * 16 * S20 + ks * 8) * 4));
            #pragma unroll
            for (int pl = 0; pl < 2; pl++) {
                uint4 bv = *(const uint4*)&Bc[(ks * 4 + wn * 2 + pl) * 128 + lane * 4];
                uint32_t bfe[2] = { bv.x, bv.y };
                uint32_t bfo[2] = { bv.z, bv.w };
                mma_tf32(acc[0][2*pl  ], af[0], bfe);
                mma_tf32(acc[1][2*pl  ], af[1], bfe);
                mma_tf32(acc[0][2*pl+1], af[0], bfo);
                mma_tf32(acc[1][2*pl+1], af[1], bfo);
            }
        }
    }

    #pragma unroll
    for (int mt = 0; mt < 2; mt++) {
        #pragma unroll
        for (int half = 0; half < 2; half++) {
            int m = m0 + wm * 32 + mt * 16 + half * 8 + lq;
            float* rowp = out + (size_t)m * 1024 + nb * 64;
            #pragma unroll
            for (int nt = 0; nt < 4; nt++) {
                int n = wn * 32 + nt * 8 + 2 * lr;
                float2 v;
                v.x = acc[mt][nt][half * 2 + 0] + bo[nb * 64 + n];
                v.y = acc[mt][nt][half * 2 + 1] + bo[nb * 64 + n + 1];
                *(float2*)(rowp + n) = v;
            }
        }
    }
}

// ---------------------------------------------------------------------------
extern "C" void kernel_launch(void* const* d_in, const int* in_sizes, int n_in,
                              void* d_out, int out_size)
{
    const float* x  = (const float*)d_in[0];
    const float* Wq = (const float*)d_in[1];
    const float* bq = (const float*)d_in[2];
    const float* Wk = (const float*)d_in[3];
    const float* bk = (const float*)d_in[4];
    const float* Wv = (const float*)d_in[5];
    const float* bv = (const float*)d_in[6];
    const float* Wo = (const float*)d_in[7];
    const float* bo = (const float*)d_in[8];
    float* out = (float*)d_out;

    static bool attr_done = false;
    if (!attr_done) {
        cudaFuncSetAttribute(qkv_mma, cudaFuncAttributeMaxDynamicSharedMemorySize, QKV_SMEM);
        cudaFuncSetAttribute(outproj_mma, cudaFuncAttributeMaxDynamicSharedMemorySize, OP_SMEM);
        attr_done = true;
    }

    cvt_weights<<<256, 256>>>(Wq, Wk, Wv, Wo);

    qkv_mma<<<MQKV / 64, 256, QKV_SMEM>>>(x, bq, bk, bv);

    dim3 g2(BB_ * HH_, SP_ / 128);
    attn_mma<<<g2, 256>>>();

    dim3 g3(MOUT / 128, EE_ / 64);
    outproj_mma<<<g3, 256, OP_SMEM>>>(bo, out);
}

// round 13
// speedup vs baseline: 1.1419x; 1.0242x over previous
#include <cuda_runtime.h>
#include <stdint.h>

// Problem constants
#define BB_  4
#define SS_  8192
#define EE_  1024
#define HH_  16
#define DD_  64
#define SP_  512
#define MQKV (BB_*SS_)
#define MOUT (BB_*SP_)

// Scratch: q/k/v/ctx hold tf32 bit patterns; weights pre-converted AND
// pre-swizzled into mma-fragment order.
__device__ uint32_t g_q[BB_*HH_*SP_*DD_];     // [B,H,S',D] tf32 bits
__device__ uint32_t g_k[BB_*HH_*SP_*DD_];
__device__ uint32_t g_v[BB_*HH_*SP_*DD_];
__device__ uint32_t g_ctx[BB_*SP_*EE_];       // [B,S',E]  tf32 bits
__device__ uint32_t g_wqkv[192*EE_];          // fragment-ordered [Wq;Wk;Wv]
__device__ uint32_t g_wo[EE_*EE_];            // fragment-ordered Wo (128-wide n-blocks)

// ---------------------------------------------------------------------------
// helpers
// ---------------------------------------------------------------------------
__device__ __forceinline__ uint32_t f2tf32(float f) {
    uint32_t u;
    asm("cvt.rna.tf32.f32 %0, %1;" : "=r"(u) : "f"(f));
    return u;
}

__device__ __forceinline__ void mma_tf32(float c[4], const uint32_t a[4], const uint32_t b[2]) {
    asm volatile(
        "mma.sync.aligned.m16n8k8.row.col.f32.tf32.tf32.f32 "
        "{%0,%1,%2,%3}, {%4,%5,%6,%7}, {%8,%9}, {%0,%1,%2,%3};\n"
        : "+f"(c[0]), "+f"(c[1]), "+f"(c[2]), "+f"(c[3])
        : "r"(a[0]), "r"(a[1]), "r"(a[2]), "r"(a[3]), "r"(b[0]), "r"(b[1]));
}

__device__ __forceinline__ void ldsm_x4(uint32_t r[4], uint32_t addr) {
    asm volatile("ldmatrix.sync.aligned.m8n8.x4.shared.b16 {%0,%1,%2,%3}, [%4];"
                 : "=r"(r[0]), "=r"(r[1]), "=r"(r[2]), "=r"(r[3]) : "r"(addr));
}

__device__ __forceinline__ uint32_t smem_u32(const void* p) {
    return (uint32_t)__cvta_generic_to_shared(p);
}
#define CP16(dst, src) asm volatile("cp.async.cg.shared.global [%0], [%1], 16;\n" :: "r"(dst), "l"(src))
#define CP_COMMIT()    asm volatile("cp.async.commit_group;\n" ::: "memory")
#define CP_WAIT1()     asm volatile("cp.async.wait_group 1;\n" ::: "memory")

#define S20 20   // smem row stride (80B): LDSM phases conflict-free, 16B-aligned

// Fragment-pair tile: 16 n-rows x 8 k, 128 u32.
__device__ __forceinline__ int frag_idx(int n16, int k8) {
    return ((n16 & 7) * 4 + (k8 & 3)) * 4 + ((n16 >> 3) << 1) + (k8 >> 2);
}

// ---------------------------------------------------------------------------
// Kernel 0: pre-convert + pre-swizzle weights (once per launch, ~5us)
// g_wqkv: addr = ((it*2+ks)*12 + n/16)*128 + frag_idx(n%16, k%8)
// g_wo  : nb=n/128, nn=n%128: addr = (((nb*64+it)*2+ks)*8 + nn/16)*128 + frag_idx(nn%16,k%8)
// ---------------------------------------------------------------------------
__global__ __launch_bounds__(256)
void cvt_weights(const float* __restrict__ Wq, const float* __restrict__ Wk,
                 const float* __restrict__ Wv, const float* __restrict__ Wo)
{
    const int idx = blockIdx.x * 256 + threadIdx.x;   // 0..65535
    const int row = idx >> 10;
    const int k   = idx & 1023;
    const int it  = k >> 4;
    const int ks  = (k >> 3) & 1;
    const int k8  = k & 7;

    {
        const float* Ws[3] = { Wq, Wk, Wv };
        #pragma unroll
        for (int mat = 0; mat < 3; mat++) {
            int n = mat * 64 + row;
            int addr = ((it * 2 + ks) * 12 + (n >> 4)) * 128 + frag_idx(n & 15, k8);
            g_wqkv[addr] = f2tf32(Ws[mat][row * 1024 + k]);
        }
    }
    #pragma unroll
    for (int j = 0; j < 16; j++) {
        int e  = idx + j * 65536;
        int n  = e >> 10;
        int kk = e & 1023;
        int it2 = kk >> 4, ks2 = (kk >> 3) & 1, k82 = kk & 7;
        int nb = n >> 7, nn = n & 127;
        int addr = (((nb * 64 + it2) * 2 + ks2) * 8 + (nn >> 4)) * 128 + frag_idx(nn & 15, k82);
        g_wo[addr] = f2tf32(Wo[(size_t)n * 1024 + kk]);
    }
}

// ---------------------------------------------------------------------------
// Kernel 1: fused QKV projection (R11 version).  BM=64, BN=192, BK=16,
// 256 thr / 8 warps, warp tile 32m x 48n.  Grid 512 -> 2 CTAs/SM.
// ---------------------------------------------------------------------------
#define QKV_ASTG (64 * S20)    // 1280 u32
#define QKV_BSTG 3072          // u32
#define QKV_SMEM ((3 * QKV_ASTG + 3 * QKV_BSTG) * 4)   // 52.2 KB

__global__ __launch_bounds__(256)
void qkv_mma(const float* __restrict__ x,
             const float* __restrict__ bq, const float* __restrict__ bk,
             const float* __restrict__ bv)
{
    extern __shared__ uint32_t sm[];
    uint32_t* As = sm;                      // 3 stages of [64][S20]
    uint32_t* Bs = sm + 3 * QKV_ASTG;       // 3 stages of 3072 (fragment order)

    const int tid  = threadIdx.x;
    const int warp = tid >> 5;
    const int lane = tid & 31;
    const int wm   = warp >> 2;           // 0..1
    const int wn   = warp & 3;            // 0..3
    const int m0   = blockIdx.x * 64;
    const int lq   = lane >> 2;
    const int lr   = lane & 3;

    const int lt       = lane >> 3;
    const int lrw      = lane & 7;
    const int arow_off = (lt & 1) * 8 + lrw;
    const int akoff    = (lt >> 1) * 4;
    uint32_t a_ldsm[3];
    #pragma unroll
    for (int s = 0; s < 3; s++)
        a_ldsm[s] = smem_u32(&As[s * QKV_ASTG + (wm * 32 + arow_off) * S20 + akoff]);

    const int arow = tid >> 2;
    const int ac4  = (tid & 3) * 4;
    const float* a_src = x + (size_t)(m0 + arow) * 1024 + ac4;
    uint32_t a_dst[3];
    #pragma unroll
    for (int s = 0; s < 3; s++)
        a_dst[s] = smem_u32(&As[s * QKV_ASTG + arow * S20 + ac4]);

    uint32_t b_dst[3][3];
    #pragma unroll
    for (int s = 0; s < 3; s++)
        #pragma unroll
        for (int t = 0; t < 3; t++)
            b_dst[t][s] = smem_u32(&Bs[s * QKV_BSTG + (t * 256 + tid) * 4]);

    float acc[2][6][4];
    #pragma unroll
    for (int mt = 0; mt < 2; mt++)
        #pragma unroll
        for (int nt = 0; nt < 6; nt++)
            #pragma unroll
            for (int e = 0; e < 4; e++) acc[mt][nt][e] = 0.f;

    #pragma unroll
    for (int s = 0; s < 2; s++) {
        CP16(a_dst[s], a_src + s * 16);
        #pragma unroll
        for (int t = 0; t < 3; t++)
            CP16(b_dst[t][s], g_wqkv + s * QKV_BSTG + (t * 256 + tid) * 4);
        CP_COMMIT();
    }

    for (int it = 0; it < 64; ++it) {
        CP_WAIT1();
        __syncthreads();

        if (it + 2 < 64) {
            int s = (it + 2) % 3;
            CP16(a_dst[s], a_src + (it + 2) * 16);
            #pragma unroll
            for (int t = 0; t < 3; t++)
                CP16(b_dst[t][s], g_wqkv + (it + 2) * QKV_BSTG + (t * 256 + tid) * 4);
        }
        CP_COMMIT();

        const int cur = it % 3;
        const uint32_t* Bc = Bs + cur * QKV_BSTG;
        const uint32_t  Ab = a_ldsm[cur];

        #pragma unroll
        for (int ks = 0; ks < 2; ks++) {
            uint32_t af[2][4];
            #pragma unroll
            for (int mt = 0; mt < 2; mt++) {
                uint32_t raw[4];
                ldsm_x4(raw, Ab + (uint32_t)((mt * 16 * S20 + ks * 8) * 4));
                af[mt][0] = f2tf32(__uint_as_float(raw[0]));
                af[mt][1] = f2tf32(__uint_as_float(raw[1]));
                af[mt][2] = f2tf32(__uint_as_float(raw[2]));
                af[mt][3] = f2tf32(__uint_as_float(raw[3]));
            }
            #pragma unroll
            for (int pl = 0; pl < 3; pl++) {
                uint4 bv = *(const uint4*)&Bc[(ks * 12 + wn * 3 + pl) * 128 + lane * 4];
                uint32_t bfe[2] = { bv.x, bv.y };
                uint32_t bfo[2] = { bv.z, bv.w };
                mma_tf32(acc[0][2*pl  ], af[0], bfe);
                mma_tf32(acc[1][2*pl  ], af[1], bfe);
                mma_tf32(acc[0][2*pl+1], af[0], bfo);
                mma_tf32(acc[1][2*pl+1], af[1], bfo);
            }
        }
    }

    #pragma unroll
    for (int mt = 0; mt < 2; mt++) {
        #pragma unroll
        for (int half = 0; half < 2; half++) {
            int m  = m0 + wm * 32 + mt * 16 + half * 8 + lq;
            int bb = m >> 13;
            int s  = m & 8191;
            int sp = s >> 4;
            int h  = s & 15;
            size_t rowoff = ((size_t)(bb * 16 + h) * 512 + sp) * 64;
            #pragma unroll
            for (int nt = 0; nt < 6; nt++) {
                int n   = wn * 48 + nt * 8 + 2 * lr;
                int mat = n >> 6;
                int nn  = n & 63;
                uint32_t* dst = (mat == 0) ? g_q : (mat == 1 ? g_k : g_v);
                const float* bias = (mat == 0) ? bq : (mat == 1 ? bk : bv);
                uint2 v;
                v.x = f2tf32(acc[mt][nt][half * 2 + 0] + bias[nn]);
                v.y = f2tf32(acc[mt][nt][half * 2 + 1] + bias[nn + 1]);
                *(uint2*)(dst + rowoff + nn) = v;
            }
        }
    }
}

// ---------------------------------------------------------------------------
// Kernel 2: attention.  K-fragments now via ldmatrix.x4 (2 n-tiles per call);
// V-phase unchanged.  ks remains the ascending accumulation index (bit-identical).
// ---------------------------------------------------------------------------
#define KSTR 68
#define VSTR 72

__global__ __launch_bounds__(256)
void attn_mma()
{
    __shared__ __align__(16) uint32_t Ks[64 * KSTR];
    __shared__ __align__(16) uint32_t Vs[64 * VSTR];

    const int bh   = blockIdx.x;
    const int qt   = blockIdx.y;
    const int tid  = threadIdx.x;
    const int warp = tid >> 5;
    const int lane = tid & 31;
    const int lq   = lane >> 2;
    const int lr   = lane & 3;

    // K-LDSM per-lane address: group g=lane>>3 selects (n-half, k-half)
    const int g     = lane >> 3;
    const int rg    = lane & 7;
    const int sub_n = (g >> 1) * 8 + rg;    // 0..15 within an n16 pair
    const int koff  = (g & 1) * 4;
    const uint32_t k_ldsm = smem_u32(&Ks[sub_n * KSTR + koff]);

    const uint32_t* qbase = g_q + ((size_t)bh * 512 + qt * 128 + warp * 16) * 64;
    uint32_t qa[8][4];
    #pragma unroll
    for (int ks = 0; ks < 8; ks++) {
        qa[ks][0] = __float_as_uint(__uint_as_float(qbase[(size_t)lq       * 64 + ks * 8 + lr    ]) * 0.125f);
        qa[ks][1] = __float_as_uint(__uint_as_float(qbase[(size_t)(lq + 8) * 64 + ks * 8 + lr    ]) * 0.125f);
        qa[ks][2] = __float_as_uint(__uint_as_float(qbase[(size_t)lq       * 64 + ks * 8 + lr + 4]) * 0.125f);
        qa[ks][3] = __float_as_uint(__uint_as_float(qbase[(size_t)(lq + 8) * 64 + ks * 8 + lr + 4]) * 0.125f);
    }

    float o[8][4];
    #pragma unroll
    for (int nt = 0; nt < 8; nt++)
        #pragma unroll
        for (int e = 0; e < 4; e++) o[nt][e] = 0.f;
    float lsum0 = 0.f, lsum1 = 0.f;

    const uint32_t* kb = g_k + (size_t)bh * 512 * 64;
    const uint32_t* vb = g_v + (size_t)bh * 512 * 64;

    for (int kt = 0; kt < 8; kt++) {
        __syncthreads();
        #pragma unroll
        for (int i = 0; i < 4; i++) {
            int idx = tid + i * 256;
            int row = idx >> 4, c4 = (idx & 15) << 2;
            *(uint4*)(Ks + row * KSTR + c4) = *(const uint4*)(kb + (size_t)kt * 4096 + idx * 4);
            *(uint4*)(Vs + row * VSTR + c4) = *(const uint4*)(vb + (size_t)kt * 4096 + idx * 4);
        }
        __syncthreads();

        // S = Q @ K^T : K-frags via LDSM.x4 (ks ascending per accumulator)
        float sc[8][4];
        #pragma unroll
        for (int nt = 0; nt < 8; nt++)
            sc[nt][0] = sc[nt][1] = sc[nt][2] = sc[nt][3] = 0.f;
        #pragma unroll
        for (int ks = 0; ks < 8; ks++) {
            #pragma unroll
            for (int ntp = 0; ntp < 4; ntp++) {
                uint32_t raw[4];
                ldsm_x4(raw, k_ldsm + (uint32_t)((ntp * 16 * KSTR + ks * 8) * 4));
                uint32_t bf0[2] = { raw[0], raw[1] };
                uint32_t bf1[2] = { raw[2], raw[3] };
                mma_tf32(sc[2*ntp    ], qa[ks], bf0);
                mma_tf32(sc[2*ntp + 1], qa[ks], bf1);
            }
        }

        #pragma unroll
        for (int nt = 0; nt < 8; nt++) {
            float p0 = __expf(sc[nt][0]), p1 = __expf(sc[nt][1]);
            float p2 = __expf(sc[nt][2]), p3 = __expf(sc[nt][3]);
            sc[nt][0] = p0; sc[nt][1] = p1; sc[nt][2] = p2; sc[nt][3] = p3;
            lsum0 += p0 + p1;
            lsum1 += p2 + p3;
        }

        #pragma unroll
        for (int ks = 0; ks < 8; ks++) {
            int src  = (lane & ~3) | (lr >> 1);
            float t0 = __shfl_sync(0xffffffffu, sc[ks][0], src);
            float t1 = __shfl_sync(0xffffffffu, sc[ks][1], src);
            float t2 = __shfl_sync(0xffffffffu, sc[ks][2], src);
            float t3 = __shfl_sync(0xffffffffu, sc[ks][3], src);
            float u0 = __shfl_sync(0xffffffffu, sc[ks][0], src + 2);
            float u1 = __shfl_sync(0xffffffffu, sc[ks][1], src + 2);
            float u2 = __shfl_sync(0xffffffffu, sc[ks][2], src + 2);
            float u3 = __shfl_sync(0xffffffffu, sc[ks][3], src + 2);
            uint32_t pa[4];
            pa[0] = f2tf32((lr & 1) ? t1 : t0);
            pa[1] = f2tf32((lr & 1) ? t3 : t2);
            pa[2] = f2tf32((lr & 1) ? u1 : u0);
            pa[3] = f2tf32((lr & 1) ? u3 : u2);
            #pragma unroll
            for (int ntd = 0; ntd < 8; ntd++) {
                uint32_t bf[2];
                bf[0] = Vs[(ks * 8 + lr    ) * VSTR + ntd * 8 + lq];
                bf[1] = Vs[(ks * 8 + lr + 4) * VSTR + ntd * 8 + lq];
                mma_tf32(o[ntd], pa, bf);
            }
        }
    }

    lsum0 += __shfl_xor_sync(0xffffffffu, lsum0, 1);
    lsum0 += __shfl_xor_sync(0xffffffffu, lsum0, 2);
    lsum1 += __shfl_xor_sync(0xffffffffu, lsum1, 1);
    lsum1 += __shfl_xor_sync(0xffffffffu, lsum1, 2);
    const float inv0 = 1.f / lsum0;
    const float inv1 = 1.f / lsum1;

    const int bb = bh >> 4, h = bh & 15;
    const int qrow0 = qt * 128 + warp * 16 + lq;
    uint32_t* out0 = g_ctx + ((size_t)(bb * 512 + qrow0)) * 1024 + h * 64;
    uint32_t* out1 = out0 + (size_t)8 * 1024;
    #pragma unroll
    for (int ntd = 0; ntd < 8; ntd++) {
        uint2 v0 = { f2tf32(o[ntd][0] * inv0), f2tf32(o[ntd][1] * inv0) };
        uint2 v1 = { f2tf32(o[ntd][2] * inv1), f2tf32(o[ntd][3] * inv1) };
        *(uint2*)(out0 + ntd * 8 + 2 * lr) = v0;
        *(uint2*)(out1 + ntd * 8 + 2 * lr) = v1;
    }
}

// ---------------------------------------------------------------------------
// Kernel 3: output projection (R10 version — the 34.3us measurement).
// BM=128, BN=128, BK=16, 512 thr / 16 warps, warp tile 32m x 32n.
// ---------------------------------------------------------------------------
#define OP_ASTG (128 * S20)   // 2560 u32
#define OP_BSTG 2048          // u32
#define OP_SMEM ((3 * OP_ASTG + 3 * OP_BSTG) * 4)

__global__ __launch_bounds__(512)
void outproj_mma(const float* __restrict__ bo, float* __restrict__ out)
{
    extern __shared__ uint32_t sm[];
    uint32_t* As = sm;
    uint32_t* Bs = sm + 3 * OP_ASTG;

    const int tid  = threadIdx.x;
    const int warp = tid >> 5;
    const int lane = tid & 31;
    const int wm   = warp >> 2;
    const int wn   = warp & 3;
    const int m0   = blockIdx.x * 128;
    const int nb   = blockIdx.y;
    const int lq   = lane >> 2;
    const int lr   = lane & 3;

    const int lt       = lane >> 3;
    const int lrw      = lane & 7;
    const int arow_off = (lt & 1) * 8 + lrw;
    const int akoff    = (lt >> 1) * 4;
    uint32_t a_ldsm[3];
    #pragma unroll
    for (int s = 0; s < 3; s++)
        a_ldsm[s] = smem_u32(&As[s * OP_ASTG + (wm * 32 + arow_off) * S20 + akoff]);

    const int arow = tid >> 2;
    const int ac4  = (tid & 3) * 4;
    const uint32_t* a_src = g_ctx + (size_t)(m0 + arow) * 1024 + ac4;
    uint32_t a_dst[3], b_dst[3];
    #pragma unroll
    for (int s = 0; s < 3; s++) {
        a_dst[s] = smem_u32(&As[s * OP_ASTG + arow * S20 + ac4]);
        b_dst[s] = smem_u32(&Bs[s * OP_BSTG + tid * 4]);
    }
    const uint32_t* b_base = g_wo + (size_t)nb * 64 * OP_BSTG;

    float acc[2][4][4];
    #pragma unroll
    for (int mt = 0; mt < 2; mt++)
        #pragma unroll
        for (int nt = 0; nt < 4; nt++)
            #pragma unroll
            for (int e = 0; e < 4; e++) acc[mt][nt][e] = 0.f;

    #pragma unroll
    for (int s = 0; s < 2; s++) {
        CP16(a_dst[s], a_src + s * 16);
        CP16(b_dst[s], b_base + s * OP_BSTG + tid * 4);
        CP_COMMIT();
    }

    for (int it = 0; it < 64; ++it) {
        CP_WAIT1();
        __syncthreads();

        if (it + 2 < 64) {
            int s = (it + 2) % 3;
            CP16(a_dst[s], a_src + (it + 2) * 16);
            CP16(b_dst[s], b_base + (size_t)(it + 2) * OP_BSTG + tid * 4);
        }
        CP_COMMIT();

        const int cur = it % 3;
        const uint32_t* Bc = Bs + cur * OP_BSTG;
        const uint32_t  Ab = a_ldsm[cur];

        #pragma unroll
        for (int ks = 0; ks < 2; ks++) {
            uint32_t af[2][4];
            #pragma unroll
            for (int mt = 0; mt < 2; mt++)
                ldsm_x4(af[mt], Ab + (uint32_t)((mt * 16 * S20 + ks * 8) * 4));
            #pragma unroll
            for (int pl = 0; pl < 2; pl++) {
                uint4 bv = *(const uint4*)&Bc[(ks * 8 + wn * 2 + pl) * 128 + lane * 4];
                uint32_t bfe[2] = { bv.x, bv.y };
                uint32_t bfo[2] = { bv.z, bv.w };
                mma_tf32(acc[0][2*pl  ], af[0], bfe);
                mma_tf32(acc[1][2*pl  ], af[1], bfe);
                mma_tf32(acc[0][2*pl+1], af[0], bfo);
                mma_tf32(acc[1][2*pl+1], af[1], bfo);
            }
        }
    }

    #pragma unroll
    for (int mt = 0; mt < 2; mt++) {
        #pragma unroll
        for (int half = 0; half < 2; half++) {
            int m = m0 + wm * 32 + mt * 16 + half * 8 + lq;
            float* rowp = out + (size_t)m * 1024 + nb * 128;
            #pragma unroll
            for (int nt = 0; nt < 4; nt++) {
                int n = wn * 32 + nt * 8 + 2 * lr;
                float2 v;
                v.x = acc[mt][nt][half * 2 + 0] + bo[nb * 128 + n];
                v.y = acc[mt][nt][half * 2 + 1] + bo[nb * 128 + n + 1];
                *(float2*)(rowp + n) = v;
            }
        }
    }
}

// ---------------------------------------------------------------------------
extern "C" void kernel_launch(void* const* d_in, const int* in_sizes, int n_in,
                              void* d_out, int out_size)
{
    const float* x  = (const float*)d_in[0];
    const float* Wq = (const float*)d_in[1];
    const float* bq = (const float*)d_in[2];
    const float* Wk = (const float*)d_in[3];
    const float* bk = (const float*)d_in[4];
    const float* Wv = (const float*)d_in[5];
    const float* bv = (const float*)d_in[6];
    const float* Wo = (const float*)d_in[7];
    const float* bo = (const float*)d_in[8];
    float* out = (float*)d_out;

    static bool attr_done = false;
    if (!attr_done) {
        cudaFuncSetAttribute(qkv_mma, cudaFuncAttributeMaxDynamicSharedMemorySize, QKV_SMEM);
        cudaFuncSetAttribute(outproj_mma, cudaFuncAttributeMaxDynamicSharedMemorySize, OP_SMEM);
        attr_done = true;
    }

    cvt_weights<<<256, 256>>>(Wq, Wk, Wv, Wo);

    qkv_mma<<<MQKV / 64, 256, QKV_SMEM>>>(x, bq, bk, bv);

    dim3 g2(BB_ * HH_, SP_ / 128);
    attn_mma<<<g2, 256>>>();

    dim3 g3(MOUT / 128, EE_ / 128);
    outproj_mma<<<g3, 512, OP_SMEM>>>(bo, out);
}